// round 16
// baseline (speedup 1.0000x reference)
#include <cuda_runtime.h>
#include <math.h>

#define EDG 24000
#define NN  8000
#define IV3 0.5773502691896257645f  // 1/sqrt(3)

// ---------------- static device scratch ----------------
__device__ float g_h   [EDG * 128];
__device__ float g_w   [EDG * 4608];       // per-edge weights (442 MB)
__device__ float g_nm  [NN * 112];
__device__ float g_FA  [NN * 2048];
__device__ float g_gsgg[NN * 48];
__device__ float g_FB  [NN * 3 * 2560];    // 246 MB
__device__ float g_gvf [NN * 3 * 32];
__device__ float g_xg  [NN * 112];
__device__ float g_sums[NN * 112];
__device__ float g_cnt [NN];
__device__ float g_th  [NN * 112];
__device__ float g_WA  [2048 * 48];
__device__ float g_WB  [2560 * 32];

// ---------------- f32x2 helpers ----------------
__device__ __forceinline__ unsigned long long dup_f32x2(float v) {
    unsigned long long r;
    asm("mov.b64 %0, {%1, %1};" : "=l"(r) : "f"(v));
    return r;
}
__device__ __forceinline__ void fma_f32x2(unsigned long long& d,
                                          unsigned long long a, unsigned long long b) {
    asm("fma.rn.f32x2 %0, %1, %2, %0;" : "+l"(d) : "l"(a), "l"(b));
}
__device__ __forceinline__ void unpack_f32x2(unsigned long long v, float& lo, float& hi) {
    asm("mov.b64 {%0, %1}, %2;" : "=f"(lo), "=f"(hi) : "l"(v));
}

// ---------------- zero accumulators ----------------
__global__ void zero_kernel() {
    int i = blockIdx.x * blockDim.x + threadIdx.x;
    const int T0 = NN * 112, T1 = 2 * NN * 112, T2 = 2 * NN * 112 + NN;
    if (i < T0)      g_nm[i] = 0.f;
    else if (i < T1) g_sums[i - T0] = 0.f;
    else if (i < T2) g_cnt[i - T1] = 0.f;
}

// ---------------- pack gate weight matrices ----------------
__global__ void prep_w_kernel(const float* __restrict__ Wg000, const float* __restrict__ Wg110,
                              const float* __restrict__ Wg001, const float* __restrict__ Wg111,
                              const float* __restrict__ Wg012, const float* __restrict__ Wg102) {
    int idx = blockIdx.x * blockDim.x + threadIdx.x;
    if (idx < 2048 * 48) {
        int k = idx / 48, j = idx % 48;
        float v;
        if (k < 1024) {
            int u = k >> 6, vv = k & 63;
            v = (j < 16) ? Wg000[(u * 64 + vv) * 16 + j]
                         : Wg001[(u * 64 + vv) * 32 + (j - 16)];
        } else {
            int kk = k - 1024; int u = kk >> 5, vv = kk & 31;
            v = (j < 16) ? Wg110[(u * 32 + vv) * 16 + j]
                         : Wg111[(u * 32 + vv) * 32 + (j - 16)];
        }
        g_WA[idx] = v;
    }
    int idx2 = idx - 2048 * 48;
    if (idx2 >= 0 && idx2 < 2560 * 32) {
        int k = idx2 / 32, w = idx2 & 31;
        float v;
        if (k < 512) { int u = k >> 5, vv = k & 31; v = Wg012[(u * 32 + vv) * 32 + w]; }
        else { int kk = k - 512; int u = kk >> 6, vv = kk & 63; v = Wg102[(u * 64 + vv) * 32 + w]; }
        g_WB[idx2] = v;
    }
}

// ---------------- radial MLP ----------------
__global__ void radial_kernel(const float* __restrict__ ea, const float* __restrict__ W1, float scale) {
    int idx = blockIdx.x * blockDim.x + threadIdx.x;
    if (idx >= EDG * 128) return;
    int e = idx >> 7, k = idx & 127;
    const float* a = ea + e * 4;
    float v = 0.5f * (a[0] * W1[k] + a[1] * W1[128 + k] + a[2] * W1[256 + k] + a[3] * W1[384 + k]);
    float s = v / (1.0f + expf(-v));
    g_h[idx] = scale * s;
}

// ---------------- big GEMM with packed f32x2 FMA (R12 version, measured 636us) ----------------
#define GK 128
#define GN 4608
__global__ void __launch_bounds__(256) gemm_big(const float* __restrict__ A,
                                                const float* __restrict__ B,
                                                float* __restrict__ C, int M) {
    __shared__ float As[16][132];   // transposed A tile: As[kk][m]
    __shared__ float Bs[16][132];   // Bs[kk][n]
    const int tid = threadIdx.x;
    const int bm = blockIdx.y * 128;
    const int bn = blockIdx.x * 128;
    const int tm = (tid >> 4) << 3;
    const int tn = (tid & 15) << 3;

    unsigned long long acc[8][4];
#pragma unroll
    for (int i = 0; i < 8; i++)
#pragma unroll
        for (int j = 0; j < 4; j++) acc[i][j] = 0ULL;

    for (int k0 = 0; k0 < GK; k0 += 16) {
#pragma unroll
        for (int r = 0; r < 2; r++) {
            int f = tid + r * 256;
            int arow = f >> 2, acol = (f & 3) << 2;
            float4 v = make_float4(0.f, 0.f, 0.f, 0.f);
            int gm = bm + arow;
            if (gm < M) v = *(const float4*)(A + (size_t)gm * GK + k0 + acol);
            As[acol + 0][arow] = v.x;
            As[acol + 1][arow] = v.y;
            As[acol + 2][arow] = v.z;
            As[acol + 3][arow] = v.w;
            int brow = f >> 5, bcol = (f & 31) << 2;
            float4 w = *(const float4*)(B + (size_t)(k0 + brow) * GN + bn + bcol);
            *(float4*)&Bs[brow][bcol] = w;
        }
        __syncthreads();
#pragma unroll
        for (int kk = 0; kk < 16; kk++) {
            float av[8];
            *(float4*)&av[0] = *(const float4*)&As[kk][tm];
            *(float4*)&av[4] = *(const float4*)&As[kk][tm + 4];
            unsigned long long b2[4];
            {
                ulonglong2 q0 = *(const ulonglong2*)&Bs[kk][tn];
                ulonglong2 q1 = *(const ulonglong2*)&Bs[kk][tn + 4];
                b2[0] = q0.x; b2[1] = q0.y; b2[2] = q1.x; b2[3] = q1.y;
            }
#pragma unroll
            for (int i = 0; i < 8; i++) {
                unsigned long long a2 = dup_f32x2(av[i]);
#pragma unroll
                for (int j = 0; j < 4; j++) fma_f32x2(acc[i][j], a2, b2[j]);
            }
        }
        __syncthreads();
    }
#pragma unroll
    for (int i = 0; i < 8; i++) {
        int gm = bm + tm + i;
        if (gm >= M) continue;
        float o[8];
#pragma unroll
        for (int j = 0; j < 4; j++) unpack_f32x2(acc[i][j], o[2 * j], o[2 * j + 1]);
        float* cp = C + (size_t)gm * GN + bn + tn;
        *(float4*)cp       = make_float4(o[0], o[1], o[2], o[3]);
        *(float4*)(cp + 4) = make_float4(o[4], o[5], o[6], o[7]);
    }
}

// ---------------- generic register-tiled fp32 GEMM ----------------
template<int BM, int BN, int BK, int TM, int TN>
__global__ void gemm_kernel(const float* __restrict__ A, const float* __restrict__ B,
                            float* __restrict__ C, int M, int N, int K) {
    __shared__ float As[BM][BK + 1];
    __shared__ float Bs[BK][BN + 4];
    const int nThreads = (BM / TM) * (BN / TN);
    const int tid = threadIdx.x;
    const int block_m = blockIdx.y * BM;
    const int block_n = blockIdx.x * BN;
    const int tm = (tid / (BN / TN)) * TM;
    const int tn = (tid % (BN / TN)) * TN;

    float acc[TM][TN];
#pragma unroll
    for (int i = 0; i < TM; i++)
#pragma unroll
        for (int j = 0; j < TN; j++) acc[i][j] = 0.f;

    for (int k0 = 0; k0 < K; k0 += BK) {
        for (int i = tid; i < BM * BK; i += nThreads) {
            int m = i / BK, kk = i % BK;
            int gm = block_m + m, gk = k0 + kk;
            float v = 0.f;
            if (gm < M && gk < K) v = A[(size_t)gm * K + gk];
            As[m][kk] = v;
        }
        for (int i = tid; i < BK * BN; i += nThreads) {
            int kk = i / BN, n = i % BN;
            int gk = k0 + kk, gn = block_n + n;
            float v = 0.f;
            if (gk < K && gn < N) v = B[(size_t)gk * N + gn];
            Bs[kk][n] = v;
        }
        __syncthreads();
#pragma unroll
        for (int kk = 0; kk < BK; kk++) {
            float av[TM], bv[TN];
#pragma unroll
            for (int i = 0; i < TM; i++) av[i] = As[tm + i][kk];
#pragma unroll
            for (int j = 0; j < TN; j++) bv[j] = Bs[kk][tn + j];
#pragma unroll
            for (int i = 0; i < TM; i++)
#pragma unroll
                for (int j = 0; j < TN; j++) acc[i][j] = fmaf(av[i], bv[j], acc[i][j]);
        }
        __syncthreads();
    }
#pragma unroll
    for (int i = 0; i < TM; i++) {
        int gm = block_m + tm + i;
        if (gm >= M) continue;
#pragma unroll
        for (int j = 0; j < TN; j++) {
            int gn = block_n + tn + j;
            if (gn < N) C[(size_t)gm * N + gn] = acc[i][j];
        }
    }
}

// ---------------- per-edge message: coalesced stream + smem-atomic contraction ----------------
// smsg layout: t000: [0:16), t110: [16:32), t011: [32:64), t101: [64 + m*32 + w)
__global__ void msg_kernel(const float* __restrict__ x, const float* __restrict__ ea,
                           const int* __restrict__ eidx, float pw_msg0, float pw_msg1) {
    int e = blockIdx.x;
    int tid = threadIdx.x;  // 128 threads
    __shared__ float sx0[64], sx1[96], sa[4], sb[32];
    __shared__ float smsg[160];

    int src = eidx[e], dst = eidx[EDG + e];
    for (int i = tid; i < 160; i += 128) {
        float v = x[src * 160 + i];
        if (i < 64) sx0[i] = v; else sx1[i - 64] = v;
        smsg[i] = 0.f;
    }
    if (tid < 4) sa[tid] = ea[e * 4 + tid];
    __syncthreads();
    if (tid < 32)
        sb[tid] = sx1[tid * 3] * sa[1] + sx1[tid * 3 + 1] * sa[2] + sx1[tid * 3 + 2] * sa[3];
    __syncthreads();

    // fully coalesced: 1152 float4 over 128 threads (9 each)
    const float4* wr4 = (const float4*)(g_w + (size_t)e * 4608);
#pragma unroll
    for (int i = 0; i < 9; i++) {
        int q = tid + 128 * i;          // float4 index
        float4 v = wr4[q];
        int o = q << 2;                 // element offset, float4-aligned
        if (o < 1024) {                 // s000: [64,16]
            int u = o >> 4, w = o & 15;
            float c = sx0[u];
            atomicAdd(&smsg[w + 0], c * v.x);
            atomicAdd(&smsg[w + 1], c * v.y);
            atomicAdd(&smsg[w + 2], c * v.z);
            atomicAdd(&smsg[w + 3], c * v.w);
        } else if (o < 3072) {          // s011: [64,32]
            int oo = o - 1024; int u = oo >> 5, w = oo & 31;
            float c = sx0[u];
            atomicAdd(&smsg[32 + w + 0], c * v.x);
            atomicAdd(&smsg[32 + w + 1], c * v.y);
            atomicAdd(&smsg[32 + w + 2], c * v.z);
            atomicAdd(&smsg[32 + w + 3], c * v.w);
        } else if (o < 4096) {          // s101: [32,32], 3 m-components
            int oo = o - 3072; int u = oo >> 5, w = oo & 31;
            float c0 = sx1[u * 3 + 0], c1 = sx1[u * 3 + 1], c2 = sx1[u * 3 + 2];
            atomicAdd(&smsg[64 + w + 0], c0 * v.x);
            atomicAdd(&smsg[64 + w + 1], c0 * v.y);
            atomicAdd(&smsg[64 + w + 2], c0 * v.z);
            atomicAdd(&smsg[64 + w + 3], c0 * v.w);
            atomicAdd(&smsg[96 + w + 0], c1 * v.x);
            atomicAdd(&smsg[96 + w + 1], c1 * v.y);
            atomicAdd(&smsg[96 + w + 2], c1 * v.z);
            atomicAdd(&smsg[96 + w + 3], c1 * v.w);
            atomicAdd(&smsg[128 + w + 0], c2 * v.x);
            atomicAdd(&smsg[128 + w + 1], c2 * v.y);
            atomicAdd(&smsg[128 + w + 2], c2 * v.z);
            atomicAdd(&smsg[128 + w + 3], c2 * v.w);
        } else {                        // s110: [32,16], coef b[u]
            int oo = o - 4096; int u = oo >> 4, w = oo & 15;
            float c = sb[u];
            atomicAdd(&smsg[16 + w + 0], c * v.x);
            atomicAdd(&smsg[16 + w + 1], c * v.y);
            atomicAdd(&smsg[16 + w + 2], c * v.z);
            atomicAdd(&smsg[16 + w + 3], c * v.w);
        }
    }
    __syncthreads();

    if (tid < 112) {
        float v;
        if (tid < 16) {
            v = pw_msg0 * (sa[0] * smsg[tid] + IV3 * smsg[16 + tid]);
        } else {
            int j = tid - 16; int w = j / 3, m = j - w * 3;
            v = pw_msg1 * IV3 * (sa[1 + m] * smsg[32 + w] + sa[0] * smsg[64 + m * 32 + w]);
        }
        atomicAdd(&g_nm[dst * 112 + tid], v);
    }
}

// ---------------- gate feature builders ----------------
__global__ void build_fa_kernel(const float* __restrict__ x, float pwg01) {
    int idx = blockIdx.x * blockDim.x + threadIdx.x;
    if (idx >= NN * 2048) return;
    int n = idx >> 11, k = idx & 2047;
    float v;
    if (k < 1024) {
        int u = k >> 6, vv = k & 63;
        v = pwg01 * g_nm[n * 112 + u] * x[n * 160 + vv];
    } else {
        int kk = k - 1024; int u = kk >> 5, vv = kk & 31;
        const float* m1 = g_nm + n * 112 + 16 + u * 3;
        const float* x1 = x + n * 160 + 64 + vv * 3;
        v = pwg01 * IV3 * (m1[0] * x1[0] + m1[1] * x1[1] + m1[2] * x1[2]);
    }
    g_FA[idx] = v;
}

__global__ void build_fb_kernel(const float* __restrict__ x, float c) {
    int idx = blockIdx.x * blockDim.x + threadIdx.x;
    if (idx >= NN * 3 * 2560) return;
    int row = idx / 2560, k = idx - row * 2560;
    int n = row / 3, m = row - n * 3;
    float v;
    if (k < 512) {
        int u = k >> 5, vv = k & 31;
        v = c * g_nm[n * 112 + u] * x[n * 160 + 64 + vv * 3 + m];
    } else {
        int kk = k - 512; int u = kk >> 6, vv = kk & 63;
        v = c * g_nm[n * 112 + 16 + u * 3 + m] * x[n * 160 + vv];
    }
    g_FB[idx] = v;
}

// ---------------- gates + masked segment scatter ----------------
__global__ void xg_kernel(const int* __restrict__ z, const int* __restrict__ can,
                          float cst_sig, float cst_tanh) {
    int idx = blockIdx.x * blockDim.x + threadIdx.x;
    if (idx >= NN * 112) return;
    int n = idx / 112, t = idx - n * 112;
    float v;
    if (t < 16) {
        v = cst_sig / (1.0f + expf(-g_gsgg[n * 48 + t]));
    } else {
        int j = t - 16; int w = j / 3, m = j - w * 3;
        float gate = cst_tanh * tanhf(g_gsgg[n * 48 + 16 + w]);
        v = gate * g_gvf[(n * 3 + m) * 32 + w];
    }
    g_xg[idx] = v;
    if (z[n] > 1) {
        atomicAdd(&g_sums[can[n] * 112 + t], v);
        if (t == 0) atomicAdd(&g_cnt[can[n]], 1.0f);
    }
}

// ---------------- th (second-order node update) ----------------
__global__ void th_kernel(const float* __restrict__ Wa, const float* __restrict__ Wb,
                          const float* __restrict__ Wc, const float* __restrict__ Wd,
                          float pwh0, float pwh1) {
    int n = blockIdx.x, tid = threadIdx.x;  // 128 threads
    __shared__ float sh[112];
    __shared__ float sD[1024];
    __shared__ float sc1[32];
    __shared__ float spart[128];
    float inv = 1.0f / fmaxf(g_cnt[n], 1.0f);
    if (tid < 112) sh[tid] = g_sums[n * 112 + tid] * inv;
    __syncthreads();
    for (int k = tid; k < 1024; k += 128) {
        int u = k >> 5, v = k & 31;
        const float* hu = sh + 16 + u * 3;
        const float* hv = sh + 16 + v * 3;
        sD[k] = hu[0] * hv[0] + hu[1] * hv[1] + hu[2] * hv[2];
    }
    if (tid < 32) {
        float acc = 0.f;
#pragma unroll
        for (int k = 0; k < 16; k++) acc += (Wb[k * 32 + tid] + Wc[tid * 16 + k]) * sh[k];
        sc1[tid] = acc;
    }
    __syncthreads();
    {
        int w = tid & 15, p = tid >> 4;
        float acc = 0.f;
        for (int k = p * 128; k < p * 128 + 128; k++) acc = fmaf(sD[k], Wd[k * 16 + w], acc);
        spart[tid] = acc;
    }
    __syncthreads();
    if (tid < 112) {
        float v;
        if (tid < 16) {
            float t0b = 0.f;
#pragma unroll
            for (int p = 0; p < 8; p++) t0b += spart[p * 16 + tid];
            float wa = 0.f;
#pragma unroll
            for (int q = 0; q < 16; q++) wa = fmaf(Wa[tid * 16 + q], sh[q], wa);
            v = pwh0 * (sh[tid] * wa + IV3 * t0b);
        } else {
            int u = (tid - 16) / 3;
            v = pwh1 * IV3 * sh[tid] * sc1[u];
        }
        g_th[n * 112 + tid] = v;
    }
}

// ---------------- final select + linear ----------------
__global__ void out_kernel(const float* __restrict__ WL0, const float* __restrict__ WL1,
                           const int* __restrict__ z, const int* __restrict__ can,
                           float* __restrict__ out) {
    int n = blockIdx.x, tid = threadIdx.x;  // 128 threads
    __shared__ float sy[112];
    bool mask = z[n] > 1;
    int c = can[n];
    const float* y = mask ? (g_th + (size_t)c * 112) : (g_xg + (size_t)n * 112);
    if (tid < 112) sy[tid] = y[tid];
    __syncthreads();
    if (tid < 112) {
        float v = 0.f;
        if (tid < 16) {
#pragma unroll
            for (int u = 0; u < 16; u++) v = fmaf(sy[u], WL0[u * 16 + tid], v);
            v *= 0.25f;
        } else {
            int j = tid - 16; int w = j / 3, m = j - w * 3;
#pragma unroll
            for (int u = 0; u < 32; u++) v = fmaf(sy[16 + u * 3 + m], WL1[u * 32 + w], v);
            v *= 0.17677669529663687f;  // 1/sqrt(32)
        }
        out[(size_t)n * 112 + tid] = v;
    }
}

// ---------------- host: normalization constants (exact np.trapz match) ----------------
static void host_csts(double& c_silu, double& c_sig, double& c_tanh) {
    const int NPT = 200001;
    const double lo = -12.0, hi = 12.0;
    const double step = (hi - lo) / (double)(NPT - 1);
    double s1 = 0.0, s2 = 0.0, s3 = 0.0;
    double p1 = 0.0, p2 = 0.0, p3 = 0.0;
    for (int i = 0; i < NPT; i++) {
        double xv = lo + step * i;
        double pdf = exp(-0.5 * xv * xv) * 0.3989422804014327;
        double sig = 1.0 / (1.0 + exp(-xv));
        double f1 = xv * sig; f1 = f1 * f1 * pdf;
        double f2 = sig * sig * pdf;
        double th = tanh(xv); double f3 = th * th * pdf;
        if (i > 0) { s1 += p1 + f1; s2 += p2 + f2; s3 += p3 + f3; }
        p1 = f1; p2 = f2; p3 = f3;
    }
    s1 *= 0.5 * step; s2 *= 0.5 * step; s3 *= 0.5 * step;
    c_silu = 1.0 / sqrt(s1);
    c_sig  = 1.0 / sqrt(s2);
    c_tanh = 1.0 / sqrt(s3);
}

extern "C" void kernel_launch(void* const* d_in, const int* in_sizes, int n_in,
                              void* d_out, int out_size) {
    const float* x     = (const float*)d_in[0];
    const float* ea    = (const float*)d_in[1];
    const float* W1    = (const float*)d_in[2];
    const float* W2    = (const float*)d_in[3];
    const float* Wg000 = (const float*)d_in[4];
    const float* Wg110 = (const float*)d_in[5];
    const float* Wg001 = (const float*)d_in[6];
    const float* Wg111 = (const float*)d_in[7];
    const float* Wg012 = (const float*)d_in[8];
    const float* Wg102 = (const float*)d_in[9];
    const float* Wa    = (const float*)d_in[10];
    const float* Wb    = (const float*)d_in[11];
    const float* Wc    = (const float*)d_in[12];
    const float* Wd    = (const float*)d_in[13];
    const float* WL0   = (const float*)d_in[14];
    const float* WL1   = (const float*)d_in[15];
    const int*   eidx  = (const int*)d_in[16];
    const int*   z     = (const int*)d_in[17];
    const int*   can   = (const int*)d_in[18];
    float* out = (float*)d_out;

    double c_silu_d, c_sig_d, c_tanh_d;
    host_csts(c_silu_d, c_sig_d, c_tanh_d);
    float radial_scale = (float)(c_silu_d / sqrt(128.0));
    float cst_sig  = (float)c_sig_d;
    float cst_tanh = (float)c_tanh_d;
    float pw_msg0 = (float)sqrt(1.0 / 96.0);
    float pw_msg1 = (float)sqrt(3.0 / 96.0);
    float pwg01   = (float)sqrt(1.0 / 2048.0);
    float pwg2c   = (float)(sqrt(3.0 / 2560.0) * (1.0 / sqrt(3.0)));
    float pwh0    = (float)sqrt(1.0 / 1040.0);
    float pwh1    = (float)sqrt(3.0 / 32.0);

    void *p_h, *p_w, *p_FA, *p_gsgg, *p_FB, *p_gvf, *p_WA, *p_WB;
    cudaGetSymbolAddress(&p_h, g_h);
    cudaGetSymbolAddress(&p_w, g_w);
    cudaGetSymbolAddress(&p_FA, g_FA);
    cudaGetSymbolAddress(&p_gsgg, g_gsgg);
    cudaGetSymbolAddress(&p_FB, g_FB);
    cudaGetSymbolAddress(&p_gvf, g_gvf);
    cudaGetSymbolAddress(&p_WA, g_WA);
    cudaGetSymbolAddress(&p_WB, g_WB);

    // 1. zero accumulators
    zero_kernel<<<(2 * NN * 112 + NN + 255) / 256, 256>>>();
    // 2. pack gate weights
    prep_w_kernel<<<(2048 * 48 + 2560 * 32 + 255) / 256, 256>>>(Wg000, Wg110, Wg001, Wg111, Wg012, Wg102);
    // 3. radial features
    radial_kernel<<<(EDG * 128 + 255) / 256, 256>>>(ea, W1, radial_scale);
    // 4. big GEMM (f32x2, single-buffered R12 version): g_w = g_h @ W2
    gemm_big<<<dim3(4608 / 128, (EDG + 127) / 128), 256>>>(
        (const float*)p_h, W2, (float*)p_w, EDG);
    // 5. message contraction + scatter (coalesced streaming + smem atomics)
    msg_kernel<<<EDG, 128>>>(x, ea, eidx, pw_msg0, pw_msg1);
    // 6. gate features A; GEMM -> gs|gg
    build_fa_kernel<<<(NN * 2048 + 255) / 256, 256>>>(x, pwg01);
    gemm_kernel<64, 48, 16, 4, 4><<<dim3(1, NN / 64), 192>>>(
        (const float*)p_FA, (const float*)p_WA, (float*)p_gsgg, NN, 48, 2048);
    // 7. gate features B; GEMM -> gv
    build_fb_kernel<<<(NN * 3 * 2560 + 255) / 256, 256>>>(x, pwg2c);
    gemm_kernel<64, 32, 16, 4, 4><<<dim3(1, NN * 3 / 64), 128>>>(
        (const float*)p_FB, (const float*)p_WB, (float*)p_gvf, NN * 3, 32, 2560);
    // 8. gates + masked segment-sum scatter
    xg_kernel<<<(NN * 112 + 255) / 256, 256>>>(z, can, cst_sig, cst_tanh);
    // 9. second-order node update
    th_kernel<<<NN, 128>>>(Wa, Wb, Wc, Wd, pwh0, pwh1);
    // 10. final select + linear
    out_kernel<<<NN, 128>>>(WL0, WL1, z, can, out);
}

// round 17
// speedup vs baseline: 1.4940x; 1.4940x over previous
#include <cuda_runtime.h>
#include <math.h>

#define EDG 24000
#define NN  8000
#define IV3 0.5773502691896257645f  // 1/sqrt(3)

// ---------------- static device scratch ----------------
__device__ float g_h   [EDG * 128];
__device__ float g_w   [EDG * 4608];       // per-edge weights (442 MB)
__device__ float g_nm  [NN * 112];
__device__ float g_FA  [NN * 2048];
__device__ float g_gsgg[NN * 48];
__device__ float g_RT  [NN * 1024 * 2];    // R_all | T_all (64 MB)
__device__ float g_gvf [NN * 3 * 32];
__device__ float g_xg  [NN * 112];
__device__ float g_sums[NN * 112];
__device__ float g_cnt [NN];
__device__ float g_th  [NN * 112];
__device__ float g_WA  [2048 * 48];
__device__ float g_WBp [64 * 1024];        // permuted Wg102: [v][u*32+w]

// ---------------- f32x2 helpers ----------------
__device__ __forceinline__ unsigned long long dup_f32x2(float v) {
    unsigned long long r;
    asm("mov.b64 %0, {%1, %1};" : "=l"(r) : "f"(v));
    return r;
}
__device__ __forceinline__ void fma_f32x2(unsigned long long& d,
                                          unsigned long long a, unsigned long long b) {
    asm("fma.rn.f32x2 %0, %1, %2, %0;" : "+l"(d) : "l"(a), "l"(b));
}
__device__ __forceinline__ void unpack_f32x2(unsigned long long v, float& lo, float& hi) {
    asm("mov.b64 {%0, %1}, %2;" : "=f"(lo), "=f"(hi) : "l"(v));
}

// ---------------- zero accumulators ----------------
__global__ void zero_kernel() {
    int i = blockIdx.x * blockDim.x + threadIdx.x;
    const int T0 = NN * 112, T1 = 2 * NN * 112, T2 = 2 * NN * 112 + NN;
    if (i < T0)      g_nm[i] = 0.f;
    else if (i < T1) g_sums[i - T0] = 0.f;
    else if (i < T2) g_cnt[i - T1] = 0.f;
}

// ---------------- pack gate weight matrices ----------------
__global__ void prep_w_kernel(const float* __restrict__ Wg000, const float* __restrict__ Wg110,
                              const float* __restrict__ Wg001, const float* __restrict__ Wg111,
                              const float* __restrict__ Wg102) {
    int idx = blockIdx.x * blockDim.x + threadIdx.x;
    if (idx < 2048 * 48) {
        int k = idx / 48, j = idx % 48;
        float v;
        if (k < 1024) {
            int u = k >> 6, vv = k & 63;
            v = (j < 16) ? Wg000[(u * 64 + vv) * 16 + j]
                         : Wg001[(u * 64 + vv) * 32 + (j - 16)];
        } else {
            int kk = k - 1024; int u = kk >> 5, vv = kk & 31;
            v = (j < 16) ? Wg110[(u * 32 + vv) * 16 + j]
                         : Wg111[(u * 32 + vv) * 32 + (j - 16)];
        }
        g_WA[idx] = v;
    }
    int idx2 = idx - 2048 * 48;
    if (idx2 >= 0 && idx2 < 64 * 1024) {   // permute Wg102[u,v,w] -> [v][u*32+w]
        int v = idx2 >> 10, rest = idx2 & 1023;
        int u = rest >> 5, w = rest & 31;
        g_WBp[idx2] = Wg102[(u * 64 + v) * 32 + w];
    }
}

// ---------------- radial MLP ----------------
__global__ void radial_kernel(const float* __restrict__ ea, const float* __restrict__ W1, float scale) {
    int idx = blockIdx.x * blockDim.x + threadIdx.x;
    if (idx >= EDG * 128) return;
    int e = idx >> 7, k = idx & 127;
    const float* a = ea + e * 4;
    float v = 0.5f * (a[0] * W1[k] + a[1] * W1[128 + k] + a[2] * W1[256 + k] + a[3] * W1[384 + k]);
    float s = v / (1.0f + expf(-v));
    g_h[idx] = scale * s;
}

// ---------------- big GEMM with packed f32x2 FMA (measured 632us) ----------------
#define GK 128
#define GN 4608
__global__ void __launch_bounds__(256) gemm_big(const float* __restrict__ A,
                                                const float* __restrict__ B,
                                                float* __restrict__ C, int M) {
    __shared__ float As[16][132];
    __shared__ float Bs[16][132];
    const int tid = threadIdx.x;
    const int bm = blockIdx.y * 128;
    const int bn = blockIdx.x * 128;
    const int tm = (tid >> 4) << 3;
    const int tn = (tid & 15) << 3;

    unsigned long long acc[8][4];
#pragma unroll
    for (int i = 0; i < 8; i++)
#pragma unroll
        for (int j = 0; j < 4; j++) acc[i][j] = 0ULL;

    for (int k0 = 0; k0 < GK; k0 += 16) {
#pragma unroll
        for (int r = 0; r < 2; r++) {
            int f = tid + r * 256;
            int arow = f >> 2, acol = (f & 3) << 2;
            float4 v = make_float4(0.f, 0.f, 0.f, 0.f);
            int gm = bm + arow;
            if (gm < M) v = *(const float4*)(A + (size_t)gm * GK + k0 + acol);
            As[acol + 0][arow] = v.x;
            As[acol + 1][arow] = v.y;
            As[acol + 2][arow] = v.z;
            As[acol + 3][arow] = v.w;
            int brow = f >> 5, bcol = (f & 31) << 2;
            float4 w = *(const float4*)(B + (size_t)(k0 + brow) * GN + bn + bcol);
            *(float4*)&Bs[brow][bcol] = w;
        }
        __syncthreads();
#pragma unroll
        for (int kk = 0; kk < 16; kk++) {
            float av[8];
            *(float4*)&av[0] = *(const float4*)&As[kk][tm];
            *(float4*)&av[4] = *(const float4*)&As[kk][tm + 4];
            unsigned long long b2[4];
            {
                ulonglong2 q0 = *(const ulonglong2*)&Bs[kk][tn];
                ulonglong2 q1 = *(const ulonglong2*)&Bs[kk][tn + 4];
                b2[0] = q0.x; b2[1] = q0.y; b2[2] = q1.x; b2[3] = q1.y;
            }
#pragma unroll
            for (int i = 0; i < 8; i++) {
                unsigned long long a2 = dup_f32x2(av[i]);
#pragma unroll
                for (int j = 0; j < 4; j++) fma_f32x2(acc[i][j], a2, b2[j]);
            }
        }
        __syncthreads();
    }
#pragma unroll
    for (int i = 0; i < 8; i++) {
        int gm = bm + tm + i;
        if (gm >= M) continue;
        float o[8];
#pragma unroll
        for (int j = 0; j < 4; j++) unpack_f32x2(acc[i][j], o[2 * j], o[2 * j + 1]);
        float* cp = C + (size_t)gm * GN + bn + tn;
        *(float4*)cp       = make_float4(o[0], o[1], o[2], o[3]);
        *(float4*)(cp + 4) = make_float4(o[4], o[5], o[6], o[7]);
    }
}

// ---------------- generic register-tiled fp32 GEMM (A row stride lda) ----------------
template<int BM, int BN, int BK, int TM, int TN>
__global__ void gemm_lda(const float* __restrict__ A, const float* __restrict__ B,
                         float* __restrict__ C, int M, int N, int K, int lda) {
    __shared__ float As[BM][BK + 1];
    __shared__ float Bs[BK][BN + 4];
    const int nThreads = (BM / TM) * (BN / TN);
    const int tid = threadIdx.x;
    const int block_m = blockIdx.y * BM;
    const int block_n = blockIdx.x * BN;
    const int tm = (tid / (BN / TN)) * TM;
    const int tn = (tid % (BN / TN)) * TN;

    float acc[TM][TN];
#pragma unroll
    for (int i = 0; i < TM; i++)
#pragma unroll
        for (int j = 0; j < TN; j++) acc[i][j] = 0.f;

    for (int k0 = 0; k0 < K; k0 += BK) {
        for (int i = tid; i < BM * BK; i += nThreads) {
            int m = i / BK, kk = i % BK;
            int gm = block_m + m, gk = k0 + kk;
            float v = 0.f;
            if (gm < M && gk < K) v = A[(size_t)gm * lda + gk];
            As[m][kk] = v;
        }
        for (int i = tid; i < BK * BN; i += nThreads) {
            int kk = i / BN, n = i % BN;
            int gk = k0 + kk, gn = block_n + n;
            float v = 0.f;
            if (gk < K && gn < N) v = B[(size_t)gk * N + gn];
            Bs[kk][n] = v;
        }
        __syncthreads();
#pragma unroll
        for (int kk = 0; kk < BK; kk++) {
            float av[TM], bv[TN];
#pragma unroll
            for (int i = 0; i < TM; i++) av[i] = As[tm + i][kk];
#pragma unroll
            for (int j = 0; j < TN; j++) bv[j] = Bs[kk][tn + j];
#pragma unroll
            for (int i = 0; i < TM; i++)
#pragma unroll
                for (int j = 0; j < TN; j++) acc[i][j] = fmaf(av[i], bv[j], acc[i][j]);
        }
        __syncthreads();
    }
#pragma unroll
    for (int i = 0; i < TM; i++) {
        int gm = block_m + tm + i;
        if (gm >= M) continue;
#pragma unroll
        for (int j = 0; j < TN; j++) {
            int gn = block_n + tn + j;
            if (gn < N) C[(size_t)gm * N + gn] = acc[i][j];
        }
    }
}

// ---------------- per-edge message contraction + scatter (R11 version) ----------------
__global__ void msg_kernel(const float* __restrict__ x, const float* __restrict__ ea,
                           const int* __restrict__ eidx, float pw_msg0, float pw_msg1) {
    int e = blockIdx.x;
    int tid = threadIdx.x;  // 128 threads
    __shared__ float sx0[64], sx1[96], sa[4], sb[32];
    __shared__ float sres[160];

    int src = eidx[e], dst = eidx[EDG + e];
    for (int i = tid; i < 160; i += 128) {
        float v = x[src * 160 + i];
        if (i < 64) sx0[i] = v; else sx1[i - 64] = v;
    }
    if (tid < 4) sa[tid] = ea[e * 4 + tid];
    __syncthreads();
    if (tid < 32)
        sb[tid] = sx1[tid * 3] * sa[1] + sx1[tid * 3 + 1] * sa[2] + sx1[tid * 3 + 2] * sa[3];
    __syncthreads();

    const float* wr = g_w + (size_t)e * 4608;
    if (tid < 16) {                       // s000
        int w = tid; float acc = 0.f;
#pragma unroll 4
        for (int u = 0; u < 64; u++) acc = fmaf(sx0[u], wr[u * 16 + w], acc);
        sres[w] = acc;
    } else if (tid < 32) {                // s110 (b = xs1 . a1)
        int w = tid - 16; float acc = 0.f;
#pragma unroll 4
        for (int u = 0; u < 32; u++) acc = fmaf(sb[u], wr[4096 + u * 16 + w], acc);
        sres[16 + w] = acc;
    } else if (tid < 64) {                // s011
        int w = tid - 32; float acc = 0.f;
#pragma unroll 4
        for (int u = 0; u < 64; u++) acc = fmaf(sx0[u], wr[1024 + u * 32 + w], acc);
        sres[32 + w] = acc;
    } else if (tid < 96) {                // s101, 3 m-components
        int w = tid - 64; float a0 = 0.f, a1 = 0.f, a2 = 0.f;
#pragma unroll 4
        for (int u = 0; u < 32; u++) {
            float v = wr[3072 + u * 32 + w];
            a0 = fmaf(sx1[u * 3 + 0], v, a0);
            a1 = fmaf(sx1[u * 3 + 1], v, a1);
            a2 = fmaf(sx1[u * 3 + 2], v, a2);
        }
        sres[64 + w] = a0; sres[96 + w] = a1; sres[128 + w] = a2;
    }
    __syncthreads();

    if (tid < 112) {
        float v;
        if (tid < 16) {
            v = pw_msg0 * (sa[0] * sres[tid] + IV3 * sres[16 + tid]);
        } else {
            int j = tid - 16; int w = j / 3, m = j - w * 3;
            v = pw_msg1 * IV3 * (sa[1 + m] * sres[32 + w] + sa[0] * sres[64 + m * 32 + w]);
        }
        atomicAdd(&g_nm[dst * 112 + tid], v);
    }
}

// ---------------- gate feature builder (FA path) ----------------
__global__ void build_fa_kernel(const float* __restrict__ x, float pwg01) {
    int idx = blockIdx.x * blockDim.x + threadIdx.x;
    if (idx >= NN * 2048) return;
    int n = idx >> 11, k = idx & 2047;
    float v;
    if (k < 1024) {
        int u = k >> 6, vv = k & 63;
        v = pwg01 * g_nm[n * 112 + u] * x[n * 160 + vv];
    } else {
        int kk = k - 1024; int u = kk >> 5, vv = kk & 31;
        const float* m1 = g_nm + n * 112 + 16 + u * 3;
        const float* x1 = x + n * 160 + 64 + vv * 3;
        v = pwg01 * IV3 * (m1[0] * x1[0] + m1[1] * x1[1] + m1[2] * x1[2]);
    }
    g_FA[idx] = v;
}

// ---------------- gv combine: gvf[n,m,w] = c*(sum_v x1*R + sum_u m1*T) ----------------
__global__ void gv_kernel(const float* __restrict__ x, float c) {
    int n = blockIdx.x, tid = threadIdx.x;  // 128 threads
    __shared__ float sR[1024], sT[1024], sx1[96], sm1[96];
    const float4* R4 = (const float4*)(g_RT + (size_t)n * 1024);
    const float4* T4 = (const float4*)(g_RT + (size_t)NN * 1024 + (size_t)n * 1024);
#pragma unroll
    for (int r = 0; r < 2; r++) {
        ((float4*)sR)[tid + 128 * r] = R4[tid + 128 * r];
        ((float4*)sT)[tid + 128 * r] = T4[tid + 128 * r];
    }
    if (tid < 96) {
        sx1[tid] = x[n * 160 + 64 + tid];
        sm1[tid] = g_nm[n * 112 + 16 + tid];
    }
    __syncthreads();
    if (tid < 96) {
        int m = tid >> 5, w = tid & 31;
        float acc = 0.f;
#pragma unroll 8
        for (int v = 0; v < 32; v++) acc = fmaf(sx1[v * 3 + m], sR[v * 32 + w], acc);
#pragma unroll 8
        for (int u = 0; u < 32; u++) acc = fmaf(sm1[u * 3 + m], sT[u * 32 + w], acc);
        g_gvf[(n * 3 + m) * 32 + w] = c * acc;
    }
}

// ---------------- gates + masked segment scatter ----------------
__global__ void xg_kernel(const int* __restrict__ z, const int* __restrict__ can,
                          float cst_sig, float cst_tanh) {
    int idx = blockIdx.x * blockDim.x + threadIdx.x;
    if (idx >= NN * 112) return;
    int n = idx / 112, t = idx - n * 112;
    float v;
    if (t < 16) {
        v = cst_sig / (1.0f + expf(-g_gsgg[n * 48 + t]));
    } else {
        int j = t - 16; int w = j / 3, m = j - w * 3;
        float gate = cst_tanh * tanhf(g_gsgg[n * 48 + 16 + w]);
        v = gate * g_gvf[(n * 3 + m) * 32 + w];
    }
    g_xg[idx] = v;
    if (z[n] > 1) {
        atomicAdd(&g_sums[can[n] * 112 + t], v);
        if (t == 0) atomicAdd(&g_cnt[can[n]], 1.0f);
    }
}

// ---------------- th (second-order node update) ----------------
__global__ void th_kernel(const float* __restrict__ Wa, const float* __restrict__ Wb,
                          const float* __restrict__ Wc, const float* __restrict__ Wd,
                          float pwh0, float pwh1) {
    int n = blockIdx.x, tid = threadIdx.x;  // 128 threads
    __shared__ float sh[112];
    __shared__ float sD[1024];
    __shared__ float sc1[32];
    __shared__ float spart[128];
    float inv = 1.0f / fmaxf(g_cnt[n], 1.0f);
    if (tid < 112) sh[tid] = g_sums[n * 112 + tid] * inv;
    __syncthreads();
    for (int k = tid; k < 1024; k += 128) {
        int u = k >> 5, v = k & 31;
        const float* hu = sh + 16 + u * 3;
        const float* hv = sh + 16 + v * 3;
        sD[k] = hu[0] * hv[0] + hu[1] * hv[1] + hu[2] * hv[2];
    }
    if (tid < 32) {
        float acc = 0.f;
#pragma unroll
        for (int k = 0; k < 16; k++) acc += (Wb[k * 32 + tid] + Wc[tid * 16 + k]) * sh[k];
        sc1[tid] = acc;
    }
    __syncthreads();
    {
        int w = tid & 15, p = tid >> 4;
        float acc = 0.f;
        for (int k = p * 128; k < p * 128 + 128; k++) acc = fmaf(sD[k], Wd[k * 16 + w], acc);
        spart[tid] = acc;
    }
    __syncthreads();
    if (tid < 112) {
        float v;
        if (tid < 16) {
            float t0b = 0.f;
#pragma unroll
            for (int p = 0; p < 8; p++) t0b += spart[p * 16 + tid];
            float wa = 0.f;
#pragma unroll
            for (int q = 0; q < 16; q++) wa = fmaf(Wa[tid * 16 + q], sh[q], wa);
            v = pwh0 * (sh[tid] * wa + IV3 * t0b);
        } else {
            int u = (tid - 16) / 3;
            v = pwh1 * IV3 * sh[tid] * sc1[u];
        }
        g_th[n * 112 + tid] = v;
    }
}

// ---------------- final select + linear ----------------
__global__ void out_kernel(const float* __restrict__ WL0, const float* __restrict__ WL1,
                           const int* __restrict__ z, const int* __restrict__ can,
                           float* __restrict__ out) {
    int n = blockIdx.x, tid = threadIdx.x;  // 128 threads
    __shared__ float sy[112];
    bool mask = z[n] > 1;
    int c = can[n];
    const float* y = mask ? (g_th + (size_t)c * 112) : (g_xg + (size_t)n * 112);
    if (tid < 112) sy[tid] = y[tid];
    __syncthreads();
    if (tid < 112) {
        float v = 0.f;
        if (tid < 16) {
#pragma unroll
            for (int u = 0; u < 16; u++) v = fmaf(sy[u], WL0[u * 16 + tid], v);
            v *= 0.25f;
        } else {
            int j = tid - 16; int w = j / 3, m = j - w * 3;
#pragma unroll
            for (int u = 0; u < 32; u++) v = fmaf(sy[16 + u * 3 + m], WL1[u * 32 + w], v);
            v *= 0.17677669529663687f;  // 1/sqrt(32)
        }
        out[(size_t)n * 112 + tid] = v;
    }
}

// ---------------- host: normalization constants (exact np.trapz match) ----------------
static void host_csts(double& c_silu, double& c_sig, double& c_tanh) {
    const int NPT = 200001;
    const double lo = -12.0, hi = 12.0;
    const double step = (hi - lo) / (double)(NPT - 1);
    double s1 = 0.0, s2 = 0.0, s3 = 0.0;
    double p1 = 0.0, p2 = 0.0, p3 = 0.0;
    for (int i = 0; i < NPT; i++) {
        double xv = lo + step * i;
        double pdf = exp(-0.5 * xv * xv) * 0.3989422804014327;
        double sig = 1.0 / (1.0 + exp(-xv));
        double f1 = xv * sig; f1 = f1 * f1 * pdf;
        double f2 = sig * sig * pdf;
        double th = tanh(xv); double f3 = th * th * pdf;
        if (i > 0) { s1 += p1 + f1; s2 += p2 + f2; s3 += p3 + f3; }
        p1 = f1; p2 = f2; p3 = f3;
    }
    s1 *= 0.5 * step; s2 *= 0.5 * step; s3 *= 0.5 * step;
    c_silu = 1.0 / sqrt(s1);
    c_sig  = 1.0 / sqrt(s2);
    c_tanh = 1.0 / sqrt(s3);
}

extern "C" void kernel_launch(void* const* d_in, const int* in_sizes, int n_in,
                              void* d_out, int out_size) {
    const float* x     = (const float*)d_in[0];
    const float* ea    = (const float*)d_in[1];
    const float* W1    = (const float*)d_in[2];
    const float* W2    = (const float*)d_in[3];
    const float* Wg000 = (const float*)d_in[4];
    const float* Wg110 = (const float*)d_in[5];
    const float* Wg001 = (const float*)d_in[6];
    const float* Wg111 = (const float*)d_in[7];
    const float* Wg012 = (const float*)d_in[8];
    const float* Wg102 = (const float*)d_in[9];
    const float* Wa    = (const float*)d_in[10];
    const float* Wb    = (const float*)d_in[11];
    const float* Wc    = (const float*)d_in[12];
    const float* Wd    = (const float*)d_in[13];
    const float* WL0   = (const float*)d_in[14];
    const float* WL1   = (const float*)d_in[15];
    const int*   eidx  = (const int*)d_in[16];
    const int*   z     = (const int*)d_in[17];
    const int*   can   = (const int*)d_in[18];
    float* out = (float*)d_out;

    double c_silu_d, c_sig_d, c_tanh_d;
    host_csts(c_silu_d, c_sig_d, c_tanh_d);
    float radial_scale = (float)(c_silu_d / sqrt(128.0));
    float cst_sig  = (float)c_sig_d;
    float cst_tanh = (float)c_tanh_d;
    float pw_msg0 = (float)sqrt(1.0 / 96.0);
    float pw_msg1 = (float)sqrt(3.0 / 96.0);
    float pwg01   = (float)sqrt(1.0 / 2048.0);
    float pwg2c   = (float)(sqrt(3.0 / 2560.0) * (1.0 / sqrt(3.0)));
    float pwh0    = (float)sqrt(1.0 / 1040.0);
    float pwh1    = (float)sqrt(3.0 / 32.0);

    void *p_h, *p_w, *p_nm, *p_FA, *p_gsgg, *p_RT, *p_WA, *p_WBp;
    cudaGetSymbolAddress(&p_h, g_h);
    cudaGetSymbolAddress(&p_w, g_w);
    cudaGetSymbolAddress(&p_nm, g_nm);
    cudaGetSymbolAddress(&p_FA, g_FA);
    cudaGetSymbolAddress(&p_gsgg, g_gsgg);
    cudaGetSymbolAddress(&p_RT, g_RT);
    cudaGetSymbolAddress(&p_WA, g_WA);
    cudaGetSymbolAddress(&p_WBp, g_WBp);
    float* RT = (float*)p_RT;

    // 1. zero accumulators
    zero_kernel<<<(2 * NN * 112 + NN + 255) / 256, 256>>>();
    // 2. pack gate weights (WA) + permute Wg102 (WBp)
    prep_w_kernel<<<(2048 * 48 + 64 * 1024 + 255) / 256, 256>>>(Wg000, Wg110, Wg001, Wg111, Wg102);
    // 3. radial features
    radial_kernel<<<(EDG * 128 + 255) / 256, 256>>>(ea, W1, radial_scale);
    // 4. big GEMM (f32x2): g_w = g_h @ W2
    gemm_big<<<dim3(4608 / 128, (EDG + 127) / 128), 256>>>(
        (const float*)p_h, W2, (float*)p_w, EDG);
    // 5. message contraction + scatter (R11 version)
    msg_kernel<<<EDG, 128>>>(x, ea, eidx, pw_msg0, pw_msg1);
    // 6. gate features A; GEMM -> gs|gg
    build_fa_kernel<<<(NN * 2048 + 255) / 256, 256>>>(x, pwg01);
    gemm_lda<64, 48, 16, 4, 4><<<dim3(1, NN / 64), 192>>>(
        (const float*)p_FA, (const float*)p_WA, (float*)p_gsgg, NN, 48, 2048, 2048);
    // 7. gv path: R = m0 @ Wg012  ([8000,16]x[16,1024]),  T = x0 @ Wg102p ([8000,64]x[64,1024])
    gemm_lda<64, 64, 16, 4, 4><<<dim3(1024 / 64, NN / 64), 256>>>(
        (const float*)p_nm, Wg012, RT, NN, 1024, 16, 112);
    gemm_lda<64, 64, 16, 4, 4><<<dim3(1024 / 64, NN / 64), 256>>>(
        x, (const float*)p_WBp, RT + (size_t)NN * 1024, NN, 1024, 64, 160);
    gv_kernel<<<NN, 128>>>(x, pwg2c);
    // 8. gates + masked segment-sum scatter
    xg_kernel<<<(NN * 112 + 255) / 256, 256>>>(z, can, cst_sig, cst_tanh);
    // 9. second-order node update
    th_kernel<<<NN, 128>>>(Wa, Wb, Wc, Wd, pwh0, pwh1);
    // 10. final select + linear
    out_kernel<<<NN, 128>>>(WL0, WL1, z, can, out);
}